// round 17
// baseline (speedup 1.0000x reference)
#include <cuda_runtime.h>
#include <cuda_bf16.h>
#include <cstdint>
#include <cstring>

#define N_NODES 100000
#define N_EDGES 1600000
#define IN_DIM  512
#define HID_DIM 64
#define NSB ((N_NODES + 1023) / 1024)   // 98 scan blocks

// fused geometry: gemm1 split GA+GB block halves at the HEAD of each grid
#define GEMM_ROWS 256
#define GA 196                           // gemm rows [0, 50176)
#define GB 195                           // gemm rows [50176, 100000)
#define EB 3125                          // edge blocks (512 edges @ 256 thr)

typedef unsigned long long u64;
typedef unsigned int u32;
#define DC_ONE_CNT (((u64)1) << 48)
#define DC_SCALE   1099511627776.0f     // 2^40
#define DC_INV     (1.0f / 1099511627776.0f)
#define DC_MASK    0xFFFFFFFFFFFFULL

// ---------------- scratch (static device globals: allocation-free) ----------
__device__ int   g_idx64;
__device__ u64   g_dc[N_NODES];          // packed: cnt<<48 | fixed-point deg
__device__ u64   g_sstate[NSB];          // lookback state: flag<<32 | value
__device__ float g_dinv[N_NODES];
__device__ int   g_rs[N_NODES + 1];
__device__ int   g_cur[N_NODES];
__device__ int   g_src[N_EDGES];
__device__ float g_w[N_EDGES];
__device__ float g_h[(size_t)N_NODES * HID_DIM];   // GEMM output (both layers)
__device__ float g_h2[(size_t)N_NODES * HID_DIM];  // layer-1 agg output
// bf16 hi/lo split of W, stored [n][k] (B operand)
__device__ __nv_bfloat16 g_b1hi[64 * IN_DIM];
__device__ __nv_bfloat16 g_b1lo[64 * IN_DIM];
__device__ __nv_bfloat16 g_b2hi[64 * HID_DIM];
__device__ __nv_bfloat16 g_b2lo[64 * HID_DIM];

// ---------------- helpers -----------------------------------------------------
__device__ __forceinline__ void mma_bf16(float* c, const uint32_t* a,
                                         uint32_t b0, uint32_t b1) {
    asm("mma.sync.aligned.m16n8k16.row.col.f32.bf16.bf16.f32 "
        "{%0,%1,%2,%3},{%4,%5,%6,%7},{%8,%9},{%0,%1,%2,%3};"
        : "+f"(c[0]), "+f"(c[1]), "+f"(c[2]), "+f"(c[3])
        : "r"(a[0]), "r"(a[1]), "r"(a[2]), "r"(a[3]), "r"(b0), "r"(b1));
}
__device__ __forceinline__ int load_idx(const void* ei, long long pos) {
    if (g_idx64) return (int)((const long long*)ei)[pos];
    return ((const int*)ei)[pos];
}
__device__ __forceinline__ uint32_t bf2u(__nv_bfloat162 t) {
    uint32_t u; memcpy(&u, &t, 4); return u;
}
// fp32 pair -> hi word (truncation, exact) + lo word (residual, rn)
__device__ __forceinline__ void split2(float x, float y, uint32_t& hi, uint32_t& lo) {
    uint32_t xb = __float_as_uint(x), yb = __float_as_uint(y);
    hi = __byte_perm(xb, yb, 0x7632);
    float lx = x - __uint_as_float(xb & 0xFFFF0000u);
    float ly = y - __uint_as_float(yb & 0xFFFF0000u);
    lo = bf2u(__floats2bfloat162_rn(lx, ly));
}

// ---------------- init: deg/cnt + scan state + dtype detect + W split --------
__global__ void init_kernel(const int* __restrict__ ei32,
                            const float* __restrict__ W1,
                            const float* __restrict__ W2) {
    int i = blockIdx.x * blockDim.x + threadIdx.x;
    if (i < N_NODES) g_dc[i] = (u64)(1.0f * DC_SCALE);   // self-loop weight only
    if (i < NSB) g_sstate[i] = 0ULL;
    if (blockIdx.x == 0 && threadIdx.x < 32) {
        int nz = 0;
#pragma unroll
        for (int j = 0; j < 4; j++) nz |= ei32[1 + 2 * (threadIdx.x * 4 + j)];
        unsigned b = __ballot_sync(0xffffffffu, nz != 0);
        if (threadIdx.x == 0) g_idx64 = (b == 0u) ? 1 : 0;
    }
    if (i < IN_DIM * 64) {
        int k = i / 64, n = i % 64;
        float w = W1[i];
        __nv_bfloat16 h = __float2bfloat16(w);
        g_b1hi[n * IN_DIM + k] = h;
        g_b1lo[n * IN_DIM + k] = __float2bfloat16(w - __bfloat162float(h));
    }
    if (i < HID_DIM * 64) {
        int k = i / 64, n = i % 64;
        float w = W2[i];
        __nv_bfloat16 h = __float2bfloat16(w);
        g_b2hi[n * HID_DIM + k] = h;
        g_b2lo[n * HID_DIM + k] = __float2bfloat16(w - __bfloat162float(h));
    }
}

// ---------------- edge-pass bodies (256 threads, 512 edges per block) --------
__device__ __forceinline__ void hist_body(int hb, const void* __restrict__ ei,
                                          const float* __restrict__ ew) {
    int base = hb * 512 + threadIdx.x;
#pragma unroll
    for (int r = 0; r < 2; r++) {
        int e = base + r * 256;
        if (e < N_EDGES) {
            int d = load_idx(ei, (long long)N_EDGES + e);
            if ((unsigned)d < (unsigned)N_NODES) {
                u64 p = DC_ONE_CNT + (u64)(ew[e] * DC_SCALE);
                atomicAdd(&g_dc[d], p);
            }
        }
    }
}

__device__ __forceinline__ void reorder_body(int rb, const void* __restrict__ ei,
                                             const float* __restrict__ ew) {
    int base = rb * 512 + threadIdx.x;
#pragma unroll
    for (int r = 0; r < 2; r++) {
        int e = base + r * 256;
        if (e < N_EDGES) {
            int s = load_idx(ei, e);
            int d = load_idx(ei, (long long)N_EDGES + e);
            if ((unsigned)d < (unsigned)N_NODES) {
                int p = atomicAdd(&g_cur[d], 1);
                if ((unsigned)s < (unsigned)N_NODES) {
                    g_src[p] = s;
                    g_w[p]   = g_dinv[s] * ew[e] * g_dinv[d];
                } else {
                    g_src[p] = 0;
                    g_w[p]   = 0.0f;
                }
            }
        }
    }
}

// ---------------- single-pass decoupled-lookback scan + dinv -----------------
__global__ void __launch_bounds__(1024) scan_kernel() {
    __shared__ int ws[32];
    __shared__ int s_excl;
    int b = blockIdx.x, tid = threadIdx.x, lane = tid & 31, wid = tid >> 5;
    int i = b * 1024 + tid;

    u64 p = (i < N_NODES) ? g_dc[i] : 0ULL;
    if (i < N_NODES) {
        float deg = (float)(p & DC_MASK) * DC_INV;
        g_dinv[i] = (deg > 0.0f) ? rsqrtf(deg) : 0.0f;
    }
    int v = (int)(p >> 48);
    int x = v;
#pragma unroll
    for (int off = 1; off < 32; off <<= 1) {
        int y = __shfl_up_sync(0xffffffffu, x, off);
        if (lane >= off) x += y;
    }
    if (lane == 31) ws[wid] = x;
    __syncthreads();
    if (wid == 0) {
        int s = ws[lane];
#pragma unroll
        for (int off = 1; off < 32; off <<= 1) {
            int y = __shfl_up_sync(0xffffffffu, s, off);
            if (lane >= off) s += y;
        }
        ws[lane] = s;
    }
    __syncthreads();
    int incl = x + (wid > 0 ? ws[wid - 1] : 0);

    if (tid == 1023 && b > 0)
        atomicExch(&g_sstate[b], (1ULL << 32) | (u32)incl);

    if (tid == 0) {
        int excl = 0;
        int pb = b - 1;
        while (pb >= 0) {
            u64 st = atomicAdd(&g_sstate[pb], 0ULL);
            u32 f = (u32)(st >> 32);
            if (f == 0u) continue;
            excl += (int)(u32)st;
            if (f == 2u) break;
            pb--;
        }
        s_excl = excl;
    }
    __syncthreads();
    int excl = s_excl;

    if (tid == 1023)
        atomicExch(&g_sstate[b], (2ULL << 32) | (u32)(excl + incl));

    if (i < N_NODES) {
        int r = excl + incl - v;
        g_rs[i] = r;
        g_cur[i] = r;
    }
    if (b == NSB - 1 && tid == 1023) g_rs[N_NODES] = excl + incl;
}

// ---------------- GEMM body: g_h[rows,64] = X @ W, bf16 3-pass ---------------
// 256 threads (8 warps), tile 256 rows x 64. Warp tile 32 rows.
// A: direct LDG.64 in fragment layout -> register convert (no smem for A).
// B: smem, double-buffered (stride 12 = conflict-free), 1 sync per chunk.
template <int K, bool FROM_G_H2>
__device__ void gemm_body(const float* __restrict__ Xext, int rowBase) {
    __shared__ uint32_t bsh[2][64][12];
    __shared__ uint32_t bsl[2][64][12];

    const float* X = FROM_G_H2 ? (const float*)g_h2 : Xext;
    const __nv_bfloat16* Bhi = (K == IN_DIM) ? g_b1hi : g_b2hi;
    const __nv_bfloat16* Blo = (K == IN_DIM) ? g_b1lo : g_b2lo;

    const int M = N_NODES;
    constexpr int CH = K / 16;
    int t = threadIdx.x, wid = t >> 5, lane = t & 31;
    int g = lane >> 2, tig = lane & 3;

    int r0 = rowBase + wid * 32 + g;
    int r1 = r0 + 16;
    int brow = t >> 2, bwu = t & 3;

    float2 av[8];
    uint2 bvh, bvl;

    {
        const int rows[4] = {r0, r0 + 8, r1, r1 + 8};
#pragma unroll
        for (int mt = 0; mt < 2; mt++)
#pragma unroll
            for (int ro = 0; ro < 2; ro++) {
                int gr = rows[mt * 2 + ro];
                bool ok = gr < M;
                av[mt * 4 + 0 * 2 + ro] = ok ? *(const float2*)(X + (size_t)gr * K + 2 * tig)
                                             : make_float2(0.f, 0.f);
                av[mt * 4 + 1 * 2 + ro] = ok ? *(const float2*)(X + (size_t)gr * K + 8 + 2 * tig)
                                             : make_float2(0.f, 0.f);
            }
        bvh = *(const uint2*)(Bhi + (size_t)brow * K + bwu * 4);
        bvl = *(const uint2*)(Blo + (size_t)brow * K + bwu * 4);
    }

    float acc[2][8][4] = {};

    for (int ch = 0; ch < CH; ch++) {
        int p = ch & 1;
        bsh[p][brow][bwu * 2]     = bvh.x;
        bsh[p][brow][bwu * 2 + 1] = bvh.y;
        bsl[p][brow][bwu * 2]     = bvl.x;
        bsl[p][brow][bwu * 2 + 1] = bvl.y;

        uint32_t ah[2][4], al[2][4];
#pragma unroll
        for (int mt = 0; mt < 2; mt++)
#pragma unroll
            for (int fi = 0; fi < 4; fi++) {
                int seg = fi >> 1, ro = fi & 1;
                float2 v = av[mt * 4 + seg * 2 + ro];
                split2(v.x, v.y, ah[mt][fi], al[mt][fi]);
            }
        __syncthreads();

        if (ch + 1 < CH) {
            int k0n = (ch + 1) * 16;
            const int rows[4] = {r0, r0 + 8, r1, r1 + 8};
#pragma unroll
            for (int mt = 0; mt < 2; mt++)
#pragma unroll
                for (int ro = 0; ro < 2; ro++) {
                    int gr = rows[mt * 2 + ro];
                    bool ok = gr < M;
                    av[mt * 4 + 0 * 2 + ro] = ok ? *(const float2*)(X + (size_t)gr * K + k0n + 2 * tig)
                                                 : make_float2(0.f, 0.f);
                    av[mt * 4 + 1 * 2 + ro] = ok ? *(const float2*)(X + (size_t)gr * K + k0n + 8 + 2 * tig)
                                                 : make_float2(0.f, 0.f);
                }
            bvh = *(const uint2*)(Bhi + (size_t)brow * K + k0n + bwu * 4);
            bvl = *(const uint2*)(Blo + (size_t)brow * K + k0n + bwu * 4);
        }

        int w0 = tig, w1 = tig + 4;
#pragma unroll
        for (int nt = 0; nt < 8; nt++) {
            int n = nt * 8 + g;
            uint32_t bh0 = bsh[p][n][w0], bh1 = bsh[p][n][w1];
            uint32_t bl0 = bsl[p][n][w0], bl1 = bsl[p][n][w1];
#pragma unroll
            for (int mt = 0; mt < 2; mt++) {
                mma_bf16(acc[mt][nt], ah[mt], bh0, bh1);
                mma_bf16(acc[mt][nt], ah[mt], bl0, bl1);
                mma_bf16(acc[mt][nt], al[mt], bh0, bh1);
            }
        }
    }

#pragma unroll
    for (int mt = 0; mt < 2; mt++) {
        int r0g = rowBase + wid * 32 + mt * 16 + g;
#pragma unroll
        for (int nt = 0; nt < 8; nt++) {
            int col = nt * 8 + tig * 2;
            if (r0g < M)
                *(float2*)(g_h + (size_t)r0g * 64 + col) =
                    make_float2(acc[mt][nt][0], acc[mt][nt][1]);
            if (r0g + 8 < M)
                *(float2*)(g_h + (size_t)(r0g + 8) * 64 + col) =
                    make_float2(acc[mt][nt][2], acc[mt][nt][3]);
        }
    }
}

// ---------------- fused launches: gemm blocks at grid HEAD -------------------
__global__ void __launch_bounds__(256) fusedA_kernel(
    const void* __restrict__ ei, const float* __restrict__ ew,
    const float* __restrict__ x) {
    if (blockIdx.x < GA) gemm_body<IN_DIM, false>(x, (int)blockIdx.x * GEMM_ROWS);
    else hist_body((int)blockIdx.x - GA, ei, ew);
}

__global__ void __launch_bounds__(256) fusedB_kernel(
    const void* __restrict__ ei, const float* __restrict__ ew,
    const float* __restrict__ x) {
    if (blockIdx.x < GB) gemm_body<IN_DIM, false>(x, (GA + (int)blockIdx.x) * GEMM_ROWS);
    else reorder_body((int)blockIdx.x - GB, ei, ew);
}

__global__ void __launch_bounds__(256) gemm2_kernel() {
    gemm_body<HID_DIM, true>(nullptr, (int)blockIdx.x * GEMM_ROWS);
}

// ---------------- aggregation: warp per node, CSR gather, no atomics --------
template <bool RELU>
__global__ void __launch_bounds__(256) agg_kernel(
    const float* __restrict__ bias, float2* __restrict__ outp) {
    const float2* H = (const float2*)g_h;
    float2* out = RELU ? (float2*)g_h2 : outp;

    int gw   = (blockIdx.x * blockDim.x + threadIdx.x) >> 5;
    int lane = threadIdx.x & 31;
    if (gw >= N_NODES) return;
    int node = gw;

    float di = g_dinv[node];
    float sn = di * di;
    float2 hv = H[(size_t)node * 32 + lane];
    float ax = sn * hv.x, ay = sn * hv.y;

    int b = g_rs[node], en = g_rs[node + 1];
    for (int i = b; i < en; i += 32) {
        int rem = en - i;
        int src = 0; float w = 0.f;
        if (lane < rem) { src = g_src[i + lane]; w = g_w[i + lane]; }
        int m = rem < 32 ? rem : 32;
        int j = 0;
        for (; j + 4 <= m; j += 4) {
            int   s0 = __shfl_sync(0xffffffffu, src, j);
            int   s1 = __shfl_sync(0xffffffffu, src, j + 1);
            int   s2 = __shfl_sync(0xffffffffu, src, j + 2);
            int   s3 = __shfl_sync(0xffffffffu, src, j + 3);
            float w0 = __shfl_sync(0xffffffffu, w, j);
            float w1 = __shfl_sync(0xffffffffu, w, j + 1);
            float w2 = __shfl_sync(0xffffffffu, w, j + 2);
            float w3 = __shfl_sync(0xffffffffu, w, j + 3);
            float2 x0 = H[(size_t)s0 * 32 + lane];
            float2 x1 = H[(size_t)s1 * 32 + lane];
            float2 x2 = H[(size_t)s2 * 32 + lane];
            float2 x3 = H[(size_t)s3 * 32 + lane];
            ax += w0 * x0.x; ay += w0 * x0.y;
            ax += w1 * x1.x; ay += w1 * x1.y;
            ax += w2 * x2.x; ay += w2 * x2.y;
            ax += w3 * x3.x; ay += w3 * x3.y;
        }
        for (; j < m; j++) {
            int   s0 = __shfl_sync(0xffffffffu, src, j);
            float w0 = __shfl_sync(0xffffffffu, w, j);
            float2 x0 = H[(size_t)s0 * 32 + lane];
            ax += w0 * x0.x; ay += w0 * x0.y;
        }
    }
    float2 bb = ((const float2*)bias)[lane];
    ax += bb.x; ay += bb.y;
    if (RELU) { ax = fmaxf(ax, 0.f); ay = fmaxf(ay, 0.f); }
    out[(size_t)node * 32 + lane] = make_float2(ax, ay);
}

// ---------------- launch -----------------------------------------------------
extern "C" void kernel_launch(void* const* d_in, const int* in_sizes, int n_in,
                              void* d_out, int out_size) {
    const float* x   = (const float*)d_in[0];
    const void*  ei  = d_in[1];
    const float* ew  = (const float*)d_in[2];
    const float* W1  = (const float*)d_in[3];
    const float* b1  = (const float*)d_in[4];
    const float* W2  = (const float*)d_in[5];
    const float* b2  = (const float*)d_in[6];
    float*       out = (float*)d_out;

    const int TPB = 256;
    int nBlocksN = (N_NODES + TPB - 1) / TPB;
    int gemm2Blocks = (N_NODES + GEMM_ROWS - 1) / GEMM_ROWS;  // 391
    int aggBlocks  = (N_NODES + 7) / 8;

    init_kernel<<<nBlocksN, TPB>>>((const int*)ei, W1, W2);
    fusedA_kernel<<<GA + EB, TPB>>>(ei, ew, x);   // gemm1 (rows 0..50175) || hist
    scan_kernel<<<NSB, 1024>>>();
    fusedB_kernel<<<GB + EB, TPB>>>(ei, ew, x);   // gemm1 (rows 50176..) || reorder

    agg_kernel<true><<<aggBlocks, TPB>>>(b1, nullptr);
    gemm2_kernel<<<gemm2Blocks, TPB>>>();
    agg_kernel<false><<<aggBlocks, TPB>>>(b2, (float2*)out);
}